// round 15
// baseline (speedup 1.0000x reference)
#include <cuda_runtime.h>
#include <math.h>

#define BB   16
#define NN   2048
#define DD   142
#define KNB  10
#define MD   16
#define EH   610
#define CPAD 640
#define QS   320
#define GN   16
#define RR   (GN*KNB)     // 160
#define ETH  640
#define RNODES 64
#define WDQ8  172
#define WE2Q8 132
#define DFS  25

typedef unsigned long long u64;

__device__ int   g_idx [BB*NN*KNB];
__device__ float g_dist[BB*NN*KNB];
__device__ float g_mi  [BB*NN*MD];
__device__ float g_hpart[(BB*NN/8)*284];
__device__ float g_fpart[(BB*NN/8)*DD];
__device__ float g_base[(size_t)BB*NN*CPAD];
__device__ float g_P   [(size_t)BB*NN*CPAD];
__device__ float g_Q   [(size_t)BB*NN*QS];
__device__ float g_R   [(size_t)BB*NN*QS];
__device__ float g_SWs [284];
__device__ float g_bW  [284];

__device__ __forceinline__ float silu(float x) {
    return __fdividef(x, 1.f + __expf(-x));
}

__device__ __forceinline__ u64 pack2(float x, float y) {
    u64 r;
    asm("mov.b64 %0, {%1, %2};" : "=l"(r) : "f"(x), "f"(y));
    return r;
}
__device__ __forceinline__ void fma2(u64 &d, u64 a, u64 b) {
    asm("fma.rn.f32x2 %0, %1, %2, %0;" : "+l"(d) : "l"(a), "l"(b));
}
__device__ __forceinline__ void add2(u64 &d, u64 a) {
    asm("add.rn.f32x2 %0, %0, %1;" : "+l"(d) : "l"(a));
}
__device__ __forceinline__ float2 unpack2(u64 v) {
    float2 r;
    asm("mov.b64 {%0, %1}, %2;" : "=f"(r.x), "=f"(r.y) : "l"(v));
    return r;
}

// ---------------- kernel 1: KNN — 2 nodes per block --------------------------
__global__ void __launch_bounds__(256) knn_kernel(const float* __restrict__ coors) {
    __shared__ float sc[NN*3];
    __shared__ float swv[8];
    __shared__ int   swi[8];
    __shared__ int   s_win[2];
    int bi0 = blockIdx.x * 2;
    int b   = bi0 >> 11;
    int i0  = bi0 & (NN - 1);
    int tid = threadIdx.x, lane = tid & 31, warp = tid >> 5;
    int h   = tid >> 7;
    int lt  = tid & 127;
    const float* cb = coors + (size_t)b * NN * 3;
    for (int idx = tid; idx < NN*3; idx += 256) sc[idx] = cb[idx];
    __syncthreads();
    int i = i0 + h;
    float cx = sc[i*3+0], cy = sc[i*3+1], cz = sc[i*3+2];
    float vals[16];
    #pragma unroll
    for (int u = 0; u < 16; u++) {
        int j = u * 128 + lt;
        float dx = cx - sc[j*3+0];
        float dy = cy - sc[j*3+1];
        float dz = cz - sc[j*3+2];
        vals[u] = dx*dx + dy*dy + dz*dz;
    }
    float lmv = vals[0]; int lmu = 0;
    #pragma unroll
    for (int u = 1; u < 16; u++)
        if (vals[u] < lmv) { lmv = vals[u]; lmu = u; }

    for (int t = 0; t < KNB; t++) {
        float bv = lmv; int bj = lmu * 128 + lt;
        #pragma unroll
        for (int off = 16; off; off >>= 1) {
            float ov = __shfl_down_sync(0xffffffffu, bv, off);
            int   oj = __shfl_down_sync(0xffffffffu, bj, off);
            if (ov < bv || (ov == bv && oj < bj)) { bv = ov; bj = oj; }
        }
        if (lane == 0) { swv[warp] = bv; swi[warp] = bj; }
        __syncthreads();
        if (lt == 0) {
            int w0 = h * 4;
            float fv = swv[w0]; int fj = swi[w0];
            #pragma unroll
            for (int w = 1; w < 4; w++) {
                float ov = swv[w0 + w]; int oj = swi[w0 + w];
                if (ov < fv || (ov == fv && oj < fj)) { fv = ov; fj = oj; }
            }
            g_idx [(bi0 + h)*KNB + t] = fj;
            g_dist[(bi0 + h)*KNB + t] = fv;
            s_win[h] = fj;
        }
        __syncthreads();
        int wj = s_win[h];
        if ((wj & 127) == lt) {
            vals[wj >> 7] = INFINITY;
            lmv = vals[0]; lmu = 0;
            #pragma unroll
            for (int u = 1; u < 16; u++)
                if (vals[u] < lmv) { lmv = vals[u]; lmu = u; }
        }
    }
}

// ---------------- kernel 1b: fold LayerNorm into Wn1 ------------------------
__global__ void lnfold_kernel(const float* __restrict__ Wn1,
                              const float* __restrict__ bn1,
                              const float* __restrict__ lng,
                              const float* __restrict__ lnb) {
    int c = threadIdx.x + blockIdx.x * 96;
    if (c >= 284) return;
    float a1 = 0.f, a2 = 0.f;
    for (int k = 0; k < DD; k++) {
        float w = Wn1[(size_t)k * 284 + c];
        a1 += lng[k] * w;
        a2 += lnb[k] * w;
    }
    g_SWs[c] = a1;
    g_bW[c]  = a2 + bn1[c];
}

// ---------------- kernel 2: prep GEMM — pre-packed A, conflict-free B -------
__global__ void __launch_bounds__(256)
prep_kernel(const float* __restrict__ feats,
            const float* __restrict__ We1, const float* __restrict__ be1,
            const float* __restrict__ Wn1, const float* __restrict__ lng) {
    __shared__ __align__(16) u64 As2u[128][18];
    __shared__ float Bs[16][64];
    int tid = threadIdx.x;
    int tx = tid & 7, ty = tid >> 3;
    int ct = blockIdx.x;
    size_t n0 = (size_t)blockIdx.y * 128;

    const float* src; int srcStride, rowOff, colbase, maxcol, outStride;
    float* outp; bool addBias = false; bool scaleLn = false;
    if (ct < 10) {
        src = We1; srcStride = EH; rowOff = 0; colbase = ct * 64;
        maxcol = EH; outp = g_base; outStride = CPAD; addBias = true;
    } else if (ct < 20) {
        src = We1; srcStride = EH; rowOff = DD; colbase = (ct - 10) * 64;
        maxcol = EH; outp = g_P; outStride = CPAD;
    } else {
        src = Wn1; srcStride = 284; rowOff = 0; colbase = (ct - 20) * 64;
        maxcol = 284; outp = g_Q; outStride = QS; scaleLn = true;
    }

    u64 acc[4][4];
    #pragma unroll
    for (int i = 0; i < 4; i++)
        #pragma unroll
        for (int j = 0; j < 4; j++) acc[i][j] = 0ull;

    for (int k0 = 0; k0 < DD; k0 += 16) {
        #pragma unroll
        for (int p = 0; p < 4; p++) {
            int idx = tid + p * 256;
            int node = idx >> 3, kp = (idx & 7) * 2;
            int k = k0 + kp;
            float2 v = make_float2(0.f, 0.f);
            if (k < DD)
                v = *(const float2*)(feats + (n0 + node) * DD + k);
            As2u[node][kp]     = pack2(v.x, v.x);
            As2u[node][kp + 1] = pack2(v.y, v.y);
        }
        #pragma unroll
        for (int p = 0; p < 2; p++) {
            int idx = tid + p * 256;
            int kk = idx >> 5, cpos = (idx & 31) * 2;
            int k = k0 + kk;
            int cl = colbase + cpos;
            float2 v = make_float2(0.f, 0.f);
            if (k < DD) {
                if (cl + 1 < maxcol)
                    v = *(const float2*)(src + (size_t)(rowOff + k) * srcStride + cl);
                else if (cl < maxcol)
                    v.x = src[(size_t)(rowOff + k) * srcStride + cl];
                if (scaleLn) {
                    float g = lng[k];
                    v.x *= g; v.y *= g;
                }
            }
            Bs[kk][cpos] = v.x; Bs[kk][cpos+1] = v.y;
        }
        __syncthreads();
        #pragma unroll
        for (int kk = 0; kk < 16; kk++) {
            ulonglong2 w01 = *(const ulonglong2*)&Bs[kk][tx*4];
            ulonglong2 w23 = *(const ulonglong2*)&Bs[kk][32 + tx*4];
            #pragma unroll
            for (int i = 0; i < 4; i++) {
                u64 pa = As2u[ty*4 + i][kk];
                fma2(acc[i][0], pa, w01.x);
                fma2(acc[i][1], pa, w01.y);
                fma2(acc[i][2], pa, w23.x);
                fma2(acc[i][3], pa, w23.y);
            }
        }
        __syncthreads();
    }

    #pragma unroll
    for (int i = 0; i < 4; i++) {
        size_t node = n0 + ty*4 + i;
        float ov[8];
        #pragma unroll
        for (int j = 0; j < 4; j++) {
            float2 v = unpack2(acc[i][j]);
            ov[2*j] = v.x; ov[2*j+1] = v.y;
        }
        #pragma unroll
        for (int j = 0; j < 4; j++) {
            int cl = colbase + tx*4 + j;
            float val = 0.f;
            if (cl < maxcol) {
                val = ov[j];
                if (addBias) val += be1[cl];
            }
            ov[j] = val;
        }
        #pragma unroll
        for (int j = 4; j < 8; j++) {
            int cl = colbase + 32 + tx*4 + (j - 4);
            float val = 0.f;
            if (cl < maxcol) {
                val = ov[j];
                if (addBias) val += be1[cl];
            }
            ov[j] = val;
        }
        float* op = outp + node * outStride + colbase;
        *(float4*)(op + tx*4)      = make_float4(ov[0], ov[1], ov[2], ov[3]);
        *(float4*)(op + 32 + tx*4) = make_float4(ov[4], ov[5], ov[6], ov[7]);
    }
}

// ---------------- kernel 3: edge — GN=16, 640 threads, same per-thread shape -
__global__ void __launch_bounds__(ETH, 1)
edge_kernel(const float* __restrict__ We1, const float* __restrict__ We2,
            const float* __restrict__ be2) {
    __shared__ int   sj [RR];
    __shared__ float sdt[RR];
    __shared__ float df_s[RR*DFS];
    __shared__ __align__(16) float wd_s[8*WDQ8];
    __shared__ __align__(16) float we2_s[8*WE2Q8];
    __shared__ __align__(16) float base_s[GN*68];
    __shared__ float Ms[RR*MD];

    int tid = threadIdx.x;
    int base_gn = blockIdx.x * GN;
    int b = base_gn >> 11;
    int cg = tid & 7;            // 8-col group
    int pp = tid >> 3;           // edge pair 0..79
    int g  = pp / 5;             // node 0..15
    int pl = pp % 5;
    int e0 = g * 10 + 2 * pl;
    int e1 = e0 + 1;

    if (tid < RR) {
        sj [tid] = g_idx [base_gn*KNB + tid];
        sdt[tid] = g_dist[base_gn*KNB + tid];
    }
    __syncthreads();

    for (int v = tid; v < RR*21; v += ETH) {
        int ee = v / 21, t = v - ee*21;
        float d = sdt[ee];
        float f;
        if (t < 10)      f = sinf(ldexpf(d, -t));
        else if (t < 20) f = cosf(ldexpf(d, -(t-10)));
        else             f = d;
        df_s[ee*DFS + t] = f;
    }

    size_t jg0 = (size_t)((b << 11) + sj[e0]);
    size_t jg1 = (size_t)((b << 11) + sj[e1]);
    u64 macc0[8] = {0,0,0,0,0,0,0,0};
    u64 macc1[8] = {0,0,0,0,0,0,0,0};

    for (int chunk = 0; chunk < 10; chunk++) {
        int c0 = chunk * 64;
        for (int v = tid; v < 21*32; v += ETH) {
            int t = v / 32, c = (v - t*32) * 2;
            int col = c0 + c;
            float2 w = make_float2(0.f, 0.f);
            if (col + 1 < EH)
                w = *(const float2*)(We1 + (size_t)(284 + t) * EH + col);
            else if (col < EH)
                w.x = We1[(size_t)(284 + t) * EH + col];
            int q = c >> 3, lq = c & 7;
            wd_s[q*WDQ8 + t*8 + lq]     = w.x;
            wd_s[q*WDQ8 + t*8 + lq + 1] = w.y;
        }
        for (int v = tid; v < 64*MD/4; v += ETH) {
            int off = v * 4;
            int row = off >> 4, m = off & 15;
            int col = c0 + row;
            float4 w = make_float4(0.f,0.f,0.f,0.f);
            if (col < EH)
                w = *(const float4*)(We2 + (size_t)col * MD + m);
            int q = row >> 3, lr = row & 7;
            *(float4*)(we2_s + q*WE2Q8 + lr*16 + m) = w;
        }
        for (int v = tid; v < GN*64/4; v += ETH) {
            int off = v * 4;
            int gg = off >> 6, c = off & 63;
            *(float4*)(base_s + gg*68 + c) =
                *(const float4*)(g_base + (size_t)(base_gn + gg) * CPAD + c0 + c);
        }
        __syncthreads();

        const float4* bp4 = (const float4*)(base_s + g*68 + cg*8);
        float4 b0 = bp4[0], b1 = bp4[1];
        const float4* pr0 = (const float4*)(g_P + jg0 * CPAD + c0 + cg*8);
        const float4* pr1 = (const float4*)(g_P + jg1 * CPAD + c0 + cg*8);
        u64 h0[4], h1[4];
        {
            float4 p0 = pr0[0], p1 = pr0[1];
            h0[0] = pack2(b0.x + p0.x, b0.y + p0.y);
            h0[1] = pack2(b0.z + p0.z, b0.w + p0.w);
            h0[2] = pack2(b1.x + p1.x, b1.y + p1.y);
            h0[3] = pack2(b1.z + p1.z, b1.w + p1.w);
        }
        {
            float4 p0 = pr1[0], p1 = pr1[1];
            h1[0] = pack2(b0.x + p0.x, b0.y + p0.y);
            h1[1] = pack2(b0.z + p0.z, b0.w + p0.w);
            h1[2] = pack2(b1.x + p1.x, b1.y + p1.y);
            h1[3] = pack2(b1.z + p1.z, b1.w + p1.w);
        }

        const float* dfp0 = df_s + e0*DFS;
        const float* dfp1 = df_s + e1*DFS;
        const float* wdq = wd_s + cg*WDQ8;
        #pragma unroll
        for (int t = 0; t < 21; t++) {
            const ulonglong2* wr = (const ulonglong2*)(wdq + t*8);
            u64 d0 = pack2(dfp0[t], dfp0[t]);
            u64 d1 = pack2(dfp1[t], dfp1[t]);
            ulonglong2 wA = wr[0], wB = wr[1];
            fma2(h0[0], d0, wA.x); fma2(h0[1], d0, wA.y);
            fma2(h0[2], d0, wB.x); fma2(h0[3], d0, wB.y);
            fma2(h1[0], d1, wA.x); fma2(h1[1], d1, wA.y);
            fma2(h1[2], d1, wB.x); fma2(h1[3], d1, wB.y);
        }
        const float* weq = we2_s + cg*WE2Q8;
        #pragma unroll
        for (int cp = 0; cp < 4; cp++) {
            const ulonglong2* wa = (const ulonglong2*)(weq + 2*cp*16);
            const ulonglong2* wb = (const ulonglong2*)(weq + 2*cp*16 + 16);
            float2 v0 = unpack2(h0[cp]);
            float2 v1 = unpack2(h1[cp]);
            u64 x00 = pack2(silu(v0.x), silu(v0.x));
            u64 x01 = pack2(silu(v0.y), silu(v0.y));
            u64 x10 = pack2(silu(v1.x), silu(v1.x));
            u64 x11 = pack2(silu(v1.y), silu(v1.y));
            ulonglong2 a0 = wa[0], a1 = wa[1], a2 = wa[2], a3 = wa[3];
            fma2(macc0[0], x00, a0.x); fma2(macc0[1], x00, a0.y);
            fma2(macc0[2], x00, a1.x); fma2(macc0[3], x00, a1.y);
            fma2(macc0[4], x00, a2.x); fma2(macc0[5], x00, a2.y);
            fma2(macc0[6], x00, a3.x); fma2(macc0[7], x00, a3.y);
            fma2(macc1[0], x10, a0.x); fma2(macc1[1], x10, a0.y);
            fma2(macc1[2], x10, a1.x); fma2(macc1[3], x10, a1.y);
            fma2(macc1[4], x10, a2.x); fma2(macc1[5], x10, a2.y);
            fma2(macc1[6], x10, a3.x); fma2(macc1[7], x10, a3.y);
            ulonglong2 c0v = wb[0], c1v = wb[1], c2v = wb[2], c3v = wb[3];
            fma2(macc0[0], x01, c0v.x); fma2(macc0[1], x01, c0v.y);
            fma2(macc0[2], x01, c1v.x); fma2(macc0[3], x01, c1v.y);
            fma2(macc0[4], x01, c2v.x); fma2(macc0[5], x01, c2v.y);
            fma2(macc0[6], x01, c3v.x); fma2(macc0[7], x01, c3v.y);
            fma2(macc1[0], x11, c0v.x); fma2(macc1[1], x11, c0v.y);
            fma2(macc1[2], x11, c1v.x); fma2(macc1[3], x11, c1v.y);
            fma2(macc1[4], x11, c2v.x); fma2(macc1[5], x11, c2v.y);
            fma2(macc1[6], x11, c3v.x); fma2(macc1[7], x11, c3v.y);
        }
        __syncthreads();
    }

    #pragma unroll
    for (int mp = 0; mp < 8; mp++) {
        add2(macc0[mp], __shfl_xor_sync(0xffffffffu, macc0[mp], 1));
        add2(macc0[mp], __shfl_xor_sync(0xffffffffu, macc0[mp], 2));
        add2(macc0[mp], __shfl_xor_sync(0xffffffffu, macc0[mp], 4));
        add2(macc1[mp], __shfl_xor_sync(0xffffffffu, macc1[mp], 1));
        add2(macc1[mp], __shfl_xor_sync(0xffffffffu, macc1[mp], 2));
        add2(macc1[mp], __shfl_xor_sync(0xffffffffu, macc1[mp], 4));
    }
    if (cg == 0) {
        #pragma unroll
        for (int mp = 0; mp < 8; mp++) {
            float2 v0 = unpack2(macc0[mp]);
            float2 v1 = unpack2(macc1[mp]);
            float bb0 = be2[2*mp], bb1 = be2[2*mp+1];
            Ms[e0*MD + 2*mp]     = silu(v0.x + bb0);
            Ms[e0*MD + 2*mp + 1] = silu(v0.y + bb1);
            Ms[e1*MD + 2*mp]     = silu(v1.x + bb0);
            Ms[e1*MD + 2*mp + 1] = silu(v1.y + bb1);
        }
    }
    __syncthreads();
    if (tid < GN*MD) {
        int gg = tid >> 4, m = tid & 15;
        float s = 0.f;
        #pragma unroll
        for (int k2 = 0; k2 < KNB; k2++) s += Ms[(gg*KNB + k2)*MD + m];
        g_mi[(size_t)(base_gn + gg)*MD + m] = s;
    }
}

// ---------------- kernel 3b: R = m_i @ Wn1[142:158]  ------------------------
__global__ void __launch_bounds__(288)
rgemm_kernel(const float* __restrict__ Wn1) {
    __shared__ u64 mi_u[RNODES][8];
    int tid = threadIdx.x;
    size_t gn0 = (size_t)blockIdx.x * RNODES;
    for (int v = tid; v < RNODES*8; v += 288) {
        int nd = v >> 3, mp = v & 7;
        float2 m2 = *(const float2*)(g_mi + (gn0 + nd) * MD + mp * 2);
        mi_u[nd][mp] = pack2(m2.x, m2.y);
    }
    __syncthreads();
    if (tid >= 284) return;
    int c = tid;
    u64 w[8];
    #pragma unroll
    for (int m = 0; m < 8; m++) {
        float w0 = Wn1[(size_t)(DD + 2*m)     * 284 + c];
        float w1 = Wn1[(size_t)(DD + 2*m + 1) * 284 + c];
        w[m] = pack2(w0, w1);
    }
    for (int nd = 0; nd < RNODES; nd++) {
        u64 acc = 0ull;
        #pragma unroll
        for (int m = 0; m < 8; m++) fma2(acc, mi_u[nd][m], w[m]);
        float2 v = unpack2(acc);
        g_R[(gn0 + nd) * QS + c] = v.x + v.y;
    }
}

// ---------------- kernel 4: LN stats + elementwise h + partial sums ----------
__global__ void __launch_bounds__(256)
node_kernel(const float* __restrict__ feats) {
    __shared__ float f_s [8 * 144];
    __shared__ float h_s [8 * 288];
    __shared__ float inv_s[8], bt_s[8];
    int tid = threadIdx.x;
    int base_gn = blockIdx.x * 8;
    int w = tid >> 5, lane = tid & 31;

    {
        int gn = base_gn + w;
        const float* fp = feats + (size_t)gn * DD;
        float s = 0.f, ss = 0.f;
        float vals[5];
        #pragma unroll
        for (int u = 0; u < 5; u++) {
            int c = lane + u * 32;
            float v = (c < DD) ? fp[c] : 0.f;
            vals[u] = v; s += v; ss += v * v;
        }
        #pragma unroll
        for (int o = 16; o; o >>= 1) {
            s  += __shfl_xor_sync(0xffffffffu, s,  o);
            ss += __shfl_xor_sync(0xffffffffu, ss, o);
        }
        float mu  = s * (1.f / DD);
        float var = ss * (1.f / DD) - mu * mu;
        float inv = rsqrtf(var + 1e-5f);
        if (lane == 0) { inv_s[w] = inv; bt_s[w] = inv * mu; }
        #pragma unroll
        for (int u = 0; u < 5; u++) {
            int c = lane + u * 32;
            if (c < DD) f_s[w * 144 + c] = vals[u];
        }
    }
    __syncthreads();

    for (int o = tid; o < 8 * 284; o += 256) {
        int g = o / 284;
        int c = o - g * 284;
        size_t gn = base_gn + g;
        float q = g_Q[gn * QS + c];
        float r = g_R[gn * QS + c];
        float val = inv_s[g] * q - bt_s[g] * g_SWs[c] + g_bW[c] + r;
        h_s[g * 288 + c] = silu(val);
    }
    __syncthreads();

    for (int c = tid; c < 284; c += 256) {
        float s = 0.f;
        #pragma unroll
        for (int gg = 0; gg < 8; gg++) s += h_s[gg * 288 + c];
        g_hpart[(size_t)blockIdx.x * 284 + c] = s;
    }
    for (int c = tid; c < DD; c += 256) {
        float s = 0.f;
        #pragma unroll
        for (int gg = 0; gg < 8; gg++) s += f_s[gg * 144 + c];
        g_fpart[(size_t)blockIdx.x * DD + c] = s;
    }
}

// ---------------- kernel 5: pool + folded stage-2 + head ---------------------
__global__ void __launch_bounds__(256)
head_kernel(const float* __restrict__ Wn2, const float* __restrict__ bn2,
            const float* __restrict__ Wout, const float* __restrict__ bout,
            float* __restrict__ out) {
    __shared__ float H[284];
    __shared__ float F[DD];
    __shared__ float red[256];
    int b = blockIdx.x, tid = threadIdx.x;
    const int bpb = NN / 8;

    for (int c = tid; c < 284; c += 256) {
        float s = 0.f;
        const float* pp = g_hpart + ((size_t)b * bpb) * 284 + c;
        for (int blk = 0; blk < bpb; blk++) s += pp[(size_t)blk * 284];
        H[c] = s;
    }
    for (int c = tid; c < DD; c += 256) {
        float s = 0.f;
        const float* pp = g_fpart + ((size_t)b * bpb) * DD + c;
        for (int blk = 0; blk < bpb; blk++) s += pp[(size_t)blk * DD];
        F[c] = s;
    }
    __syncthreads();

    float acc = 0.f;
    for (int c = tid; c < 284; c += 256) {
        const float* wr = Wn2 + (size_t)c * DD;
        float w2o = 0.f;
        for (int d = 0; d < DD; d++) w2o += wr[d] * Wout[d];
        acc += H[c] * w2o;
    }
    for (int d = tid; d < DD; d += 256)
        acc += (F[d] + (float)NN * bn2[d]) * Wout[d];
    red[tid] = acc;
    __syncthreads();
    for (int s2 = 128; s2 > 0; s2 >>= 1) {
        if (tid < s2) red[tid] += red[tid + s2];
        __syncthreads();
    }
    if (tid == 0) out[b] = red[0] * (1.f / (float)NN) + bout[0];
}

// ---------------- launch ----------------------------------------------------
extern "C" void kernel_launch(void* const* d_in, const int* in_sizes, int n_in,
                              void* d_out, int out_size) {
    const float* feats = (const float*)d_in[0];
    const float* coors = (const float*)d_in[1];
    const float* We1  = (const float*)d_in[3];
    const float* be1  = (const float*)d_in[4];
    const float* We2  = (const float*)d_in[5];
    const float* be2  = (const float*)d_in[6];
    const float* lng  = (const float*)d_in[11];
    const float* lnb  = (const float*)d_in[12];
    const float* Wn1  = (const float*)d_in[13];
    const float* bn1  = (const float*)d_in[14];
    const float* Wn2  = (const float*)d_in[15];
    const float* bn2  = (const float*)d_in[16];
    const float* Wout = (const float*)d_in[17];
    const float* bout = (const float*)d_in[18];
    float* out = (float*)d_out;

    knn_kernel<<<(BB * NN) / 2, 256>>>(coors);
    lnfold_kernel<<<3, 96>>>(Wn1, bn1, lng, lnb);
    dim3 pg(25, 256);
    prep_kernel<<<pg, 256>>>(feats, We1, be1, Wn1, lng);
    edge_kernel<<<(BB * NN) / GN, ETH>>>(We1, We2, be2);
    rgemm_kernel<<<(BB * NN) / RNODES, 288>>>(Wn1);
    node_kernel<<<(BB * NN) / 8, 256>>>(feats);
    head_kernel<<<BB, 256>>>(Wn2, bn2, Wout, bout, out);
}

// round 16
// speedup vs baseline: 1.0469x; 1.0469x over previous
#include <cuda_runtime.h>
#include <math.h>

#define BB   16
#define NN   2048
#define DD   142
#define KNB  10
#define MD   16
#define EH   610
#define CPAD 640
#define QS   320
#define GN   8
#define RR   (GN*KNB)     // 80
#define ETH  320
#define RNODES 64
#define WDQ8  172
#define WE2Q8 132
#define DFS  25

typedef unsigned long long u64;

__device__ int   g_idx [BB*NN*KNB];
__device__ float g_dist[BB*NN*KNB];
__device__ float g_mi  [BB*NN*MD];
__device__ float g_hpart[(BB*NN/8)*284];
__device__ float g_fpart[(BB*NN/8)*DD];
__device__ float g_base[(size_t)BB*NN*CPAD];
__device__ float g_P   [(size_t)BB*NN*CPAD];
__device__ float g_Q   [(size_t)BB*NN*QS];
__device__ float g_R   [(size_t)BB*NN*QS];
__device__ float g_SWs [284];
__device__ float g_bW  [284];
__device__ float g_wd_pad [21*CPAD];    // We1 dist rows, zero-padded to 640
__device__ float g_we2_pad[CPAD*MD];    // We2, zero-padded rows to 640

__device__ __forceinline__ float silu(float x) {
    return __fdividef(x, 1.f + __expf(-x));
}

__device__ __forceinline__ u64 pack2(float x, float y) {
    u64 r;
    asm("mov.b64 %0, {%1, %2};" : "=l"(r) : "f"(x), "f"(y));
    return r;
}
__device__ __forceinline__ void fma2(u64 &d, u64 a, u64 b) {
    asm("fma.rn.f32x2 %0, %1, %2, %0;" : "+l"(d) : "l"(a), "l"(b));
}
__device__ __forceinline__ void add2(u64 &d, u64 a) {
    asm("add.rn.f32x2 %0, %0, %1;" : "+l"(d) : "l"(a));
}
__device__ __forceinline__ float2 unpack2(u64 v) {
    float2 r;
    asm("mov.b64 {%0, %1}, %2;" : "=f"(r.x), "=f"(r.y) : "l"(v));
    return r;
}

// ---------------- kernel 1: KNN — 2 nodes per block --------------------------
__global__ void __launch_bounds__(256) knn_kernel(const float* __restrict__ coors) {
    __shared__ float sc[NN*3];
    __shared__ float swv[8];
    __shared__ int   swi[8];
    __shared__ int   s_win[2];
    int bi0 = blockIdx.x * 2;
    int b   = bi0 >> 11;
    int i0  = bi0 & (NN - 1);
    int tid = threadIdx.x, lane = tid & 31, warp = tid >> 5;
    int h   = tid >> 7;
    int lt  = tid & 127;
    const float* cb = coors + (size_t)b * NN * 3;
    for (int idx = tid; idx < NN*3; idx += 256) sc[idx] = cb[idx];
    __syncthreads();
    int i = i0 + h;
    float cx = sc[i*3+0], cy = sc[i*3+1], cz = sc[i*3+2];
    float vals[16];
    #pragma unroll
    for (int u = 0; u < 16; u++) {
        int j = u * 128 + lt;
        float dx = cx - sc[j*3+0];
        float dy = cy - sc[j*3+1];
        float dz = cz - sc[j*3+2];
        vals[u] = dx*dx + dy*dy + dz*dz;
    }
    float lmv = vals[0]; int lmu = 0;
    #pragma unroll
    for (int u = 1; u < 16; u++)
        if (vals[u] < lmv) { lmv = vals[u]; lmu = u; }

    for (int t = 0; t < KNB; t++) {
        float bv = lmv; int bj = lmu * 128 + lt;
        #pragma unroll
        for (int off = 16; off; off >>= 1) {
            float ov = __shfl_down_sync(0xffffffffu, bv, off);
            int   oj = __shfl_down_sync(0xffffffffu, bj, off);
            if (ov < bv || (ov == bv && oj < bj)) { bv = ov; bj = oj; }
        }
        if (lane == 0) { swv[warp] = bv; swi[warp] = bj; }
        __syncthreads();
        if (lt == 0) {
            int w0 = h * 4;
            float fv = swv[w0]; int fj = swi[w0];
            #pragma unroll
            for (int w = 1; w < 4; w++) {
                float ov = swv[w0 + w]; int oj = swi[w0 + w];
                if (ov < fv || (ov == fv && oj < fj)) { fv = ov; fj = oj; }
            }
            g_idx [(bi0 + h)*KNB + t] = fj;
            g_dist[(bi0 + h)*KNB + t] = fv;
            s_win[h] = fj;
        }
        __syncthreads();
        int wj = s_win[h];
        if ((wj & 127) == lt) {
            vals[wj >> 7] = INFINITY;
            lmv = vals[0]; lmu = 0;
            #pragma unroll
            for (int u = 1; u < 16; u++)
                if (vals[u] < lmv) { lmv = vals[u]; lmu = u; }
        }
    }
}

// ---------------- kernel 1b: lnfold + weight padding -------------------------
__global__ void lnfold_kernel(const float* __restrict__ Wn1,
                              const float* __restrict__ bn1,
                              const float* __restrict__ lng,
                              const float* __restrict__ lnb) {
    int c = threadIdx.x + blockIdx.x * 96;
    if (c >= 284) return;
    float a1 = 0.f, a2 = 0.f;
    for (int k = 0; k < DD; k++) {
        float w = Wn1[(size_t)k * 284 + c];
        a1 += lng[k] * w;
        a2 += lnb[k] * w;
    }
    g_SWs[c] = a1;
    g_bW[c]  = a2 + bn1[c];
}

__global__ void __launch_bounds__(256)
padw_kernel(const float* __restrict__ We1, const float* __restrict__ We2) {
    int idx = blockIdx.x * 256 + threadIdx.x;
    if (idx < 21 * CPAD) {
        int t = idx / CPAD, c = idx - t * CPAD;
        g_wd_pad[idx] = (c < EH) ? We1[(size_t)(284 + t) * EH + c] : 0.f;
    } else {
        int j = idx - 21 * CPAD;
        if (j < CPAD * MD) {
            int row = j >> 4;
            g_we2_pad[j] = (row < EH) ? We2[j] : 0.f;
        }
    }
}

// ---------------- kernel 2: prep GEMM — pre-packed A, conflict-free B -------
__global__ void __launch_bounds__(256)
prep_kernel(const float* __restrict__ feats,
            const float* __restrict__ We1, const float* __restrict__ be1,
            const float* __restrict__ Wn1, const float* __restrict__ lng) {
    __shared__ __align__(16) u64 As2u[128][18];
    __shared__ float Bs[16][64];
    int tid = threadIdx.x;
    int tx = tid & 7, ty = tid >> 3;
    int ct = blockIdx.x;
    size_t n0 = (size_t)blockIdx.y * 128;

    const float* src; int srcStride, rowOff, colbase, maxcol, outStride;
    float* outp; bool addBias = false; bool scaleLn = false;
    if (ct < 10) {
        src = We1; srcStride = EH; rowOff = 0; colbase = ct * 64;
        maxcol = EH; outp = g_base; outStride = CPAD; addBias = true;
    } else if (ct < 20) {
        src = We1; srcStride = EH; rowOff = DD; colbase = (ct - 10) * 64;
        maxcol = EH; outp = g_P; outStride = CPAD;
    } else {
        src = Wn1; srcStride = 284; rowOff = 0; colbase = (ct - 20) * 64;
        maxcol = 284; outp = g_Q; outStride = QS; scaleLn = true;
    }

    u64 acc[4][4];
    #pragma unroll
    for (int i = 0; i < 4; i++)
        #pragma unroll
        for (int j = 0; j < 4; j++) acc[i][j] = 0ull;

    for (int k0 = 0; k0 < DD; k0 += 16) {
        #pragma unroll
        for (int p = 0; p < 4; p++) {
            int idx = tid + p * 256;
            int node = idx >> 3, kp = (idx & 7) * 2;
            int k = k0 + kp;
            float2 v = make_float2(0.f, 0.f);
            if (k < DD)
                v = *(const float2*)(feats + (n0 + node) * DD + k);
            As2u[node][kp]     = pack2(v.x, v.x);
            As2u[node][kp + 1] = pack2(v.y, v.y);
        }
        #pragma unroll
        for (int p = 0; p < 2; p++) {
            int idx = tid + p * 256;
            int kk = idx >> 5, cpos = (idx & 31) * 2;
            int k = k0 + kk;
            int cl = colbase + cpos;
            float2 v = make_float2(0.f, 0.f);
            if (k < DD) {
                if (cl + 1 < maxcol)
                    v = *(const float2*)(src + (size_t)(rowOff + k) * srcStride + cl);
                else if (cl < maxcol)
                    v.x = src[(size_t)(rowOff + k) * srcStride + cl];
                if (scaleLn) {
                    float g = lng[k];
                    v.x *= g; v.y *= g;
                }
            }
            Bs[kk][cpos] = v.x; Bs[kk][cpos+1] = v.y;
        }
        __syncthreads();
        #pragma unroll
        for (int kk = 0; kk < 16; kk++) {
            ulonglong2 w01 = *(const ulonglong2*)&Bs[kk][tx*4];
            ulonglong2 w23 = *(const ulonglong2*)&Bs[kk][32 + tx*4];
            #pragma unroll
            for (int i = 0; i < 4; i++) {
                u64 pa = As2u[ty*4 + i][kk];
                fma2(acc[i][0], pa, w01.x);
                fma2(acc[i][1], pa, w01.y);
                fma2(acc[i][2], pa, w23.x);
                fma2(acc[i][3], pa, w23.y);
            }
        }
        __syncthreads();
    }

    #pragma unroll
    for (int i = 0; i < 4; i++) {
        size_t node = n0 + ty*4 + i;
        float ov[8];
        #pragma unroll
        for (int j = 0; j < 4; j++) {
            float2 v = unpack2(acc[i][j]);
            ov[2*j] = v.x; ov[2*j+1] = v.y;
        }
        #pragma unroll
        for (int j = 0; j < 4; j++) {
            int cl = colbase + tx*4 + j;
            float val = 0.f;
            if (cl < maxcol) {
                val = ov[j];
                if (addBias) val += be1[cl];
            }
            ov[j] = val;
        }
        #pragma unroll
        for (int j = 4; j < 8; j++) {
            int cl = colbase + 32 + tx*4 + (j - 4);
            float val = 0.f;
            if (cl < maxcol) {
                val = ov[j];
                if (addBias) val += be1[cl];
            }
            ov[j] = val;
        }
        float* op = outp + node * outStride + colbase;
        *(float4*)(op + tx*4)      = make_float4(ov[0], ov[1], ov[2], ov[3]);
        *(float4*)(op + 32 + tx*4) = make_float4(ov[4], ov[5], ov[6], ov[7]);
    }
}

// ---------------- kernel 3: edge — R14 config + padded-weight staging --------
__global__ void __launch_bounds__(ETH, 2)
edge_kernel(const float* __restrict__ be2) {
    __shared__ int   sj [RR];
    __shared__ float sdt[RR];
    __shared__ float df_s[RR*DFS];
    __shared__ __align__(16) float wd_s[8*WDQ8];
    __shared__ __align__(16) float we2_s[8*WE2Q8];
    __shared__ __align__(16) float base_s[GN*68];
    __shared__ float Ms[RR*MD];

    int tid = threadIdx.x;
    int base_gn = blockIdx.x * GN;
    int b = base_gn >> 11;
    int cg = tid & 7;
    int pp = tid >> 3;
    int g  = pp / 5;
    int pl = pp % 5;
    int e0 = g * 10 + 2 * pl;
    int e1 = e0 + 1;

    if (tid < RR) {
        sj [tid] = g_idx [base_gn*KNB + tid];
        sdt[tid] = g_dist[base_gn*KNB + tid];
    }
    __syncthreads();

    for (int v = tid; v < RR*21; v += ETH) {
        int ee = v / 21, t = v - ee*21;
        float d = sdt[ee];
        float f;
        if (t < 10)      f = sinf(ldexpf(d, -t));
        else if (t < 20) f = cosf(ldexpf(d, -(t-10)));
        else             f = d;
        df_s[ee*DFS + t] = f;
    }

    size_t jg0 = (size_t)((b << 11) + sj[e0]);
    size_t jg1 = (size_t)((b << 11) + sj[e1]);
    u64 macc0[8] = {0,0,0,0,0,0,0,0};
    u64 macc1[8] = {0,0,0,0,0,0,0,0};

    for (int chunk = 0; chunk < 10; chunk++) {
        int c0 = chunk * 64;
        // unconditional staging from padded mirrors
        for (int v = tid; v < 21*32; v += ETH) {
            int t = v / 32, c = (v - t*32) * 2;
            float2 w = *(const float2*)(g_wd_pad + t*CPAD + c0 + c);
            int q = c >> 3, lq = c & 7;
            wd_s[q*WDQ8 + t*8 + lq]     = w.x;
            wd_s[q*WDQ8 + t*8 + lq + 1] = w.y;
        }
        for (int v = tid; v < 64*MD/4; v += ETH) {
            int off = v * 4;
            int row = off >> 4, m = off & 15;
            float4 w = *(const float4*)(g_we2_pad + (size_t)(c0 + row) * MD + m);
            int q = row >> 3, lr = row & 7;
            *(float4*)(we2_s + q*WE2Q8 + lr*16 + m) = w;
        }
        for (int v = tid; v < GN*64/4; v += ETH) {
            int off = v * 4;
            int gg = off >> 6, c = off & 63;
            *(float4*)(base_s + gg*68 + c) =
                *(const float4*)(g_base + (size_t)(base_gn + gg) * CPAD + c0 + c);
        }
        __syncthreads();

        const float4* bp4 = (const float4*)(base_s + g*68 + cg*8);
        float4 b0 = bp4[0], b1 = bp4[1];
        const float4* pr0 = (const float4*)(g_P + jg0 * CPAD + c0 + cg*8);
        const float4* pr1 = (const float4*)(g_P + jg1 * CPAD + c0 + cg*8);
        u64 h0[4], h1[4];
        {
            float4 p0 = pr0[0], p1 = pr0[1];
            h0[0] = pack2(b0.x + p0.x, b0.y + p0.y);
            h0[1] = pack2(b0.z + p0.z, b0.w + p0.w);
            h0[2] = pack2(b1.x + p1.x, b1.y + p1.y);
            h0[3] = pack2(b1.z + p1.z, b1.w + p1.w);
        }
        {
            float4 p0 = pr1[0], p1 = pr1[1];
            h1[0] = pack2(b0.x + p0.x, b0.y + p0.y);
            h1[1] = pack2(b0.z + p0.z, b0.w + p0.w);
            h1[2] = pack2(b1.x + p1.x, b1.y + p1.y);
            h1[3] = pack2(b1.z + p1.z, b1.w + p1.w);
        }

        const float* dfp0 = df_s + e0*DFS;
        const float* dfp1 = df_s + e1*DFS;
        const float* wdq = wd_s + cg*WDQ8;
        #pragma unroll
        for (int t = 0; t < 21; t++) {
            const ulonglong2* wr = (const ulonglong2*)(wdq + t*8);
            u64 d0 = pack2(dfp0[t], dfp0[t]);
            u64 d1 = pack2(dfp1[t], dfp1[t]);
            ulonglong2 wA = wr[0], wB = wr[1];
            fma2(h0[0], d0, wA.x); fma2(h0[1], d0, wA.y);
            fma2(h0[2], d0, wB.x); fma2(h0[3], d0, wB.y);
            fma2(h1[0], d1, wA.x); fma2(h1[1], d1, wA.y);
            fma2(h1[2], d1, wB.x); fma2(h1[3], d1, wB.y);
        }
        const float* weq = we2_s + cg*WE2Q8;
        #pragma unroll
        for (int cp = 0; cp < 4; cp++) {
            const ulonglong2* wa = (const ulonglong2*)(weq + 2*cp*16);
            const ulonglong2* wb = (const ulonglong2*)(weq + 2*cp*16 + 16);
            float2 v0 = unpack2(h0[cp]);
            float2 v1 = unpack2(h1[cp]);
            u64 x00 = pack2(silu(v0.x), silu(v0.x));
            u64 x01 = pack2(silu(v0.y), silu(v0.y));
            u64 x10 = pack2(silu(v1.x), silu(v1.x));
            u64 x11 = pack2(silu(v1.y), silu(v1.y));
            ulonglong2 a0 = wa[0], a1 = wa[1], a2 = wa[2], a3 = wa[3];
            fma2(macc0[0], x00, a0.x); fma2(macc0[1], x00, a0.y);
            fma2(macc0[2], x00, a1.x); fma2(macc0[3], x00, a1.y);
            fma2(macc0[4], x00, a2.x); fma2(macc0[5], x00, a2.y);
            fma2(macc0[6], x00, a3.x); fma2(macc0[7], x00, a3.y);
            fma2(macc1[0], x10, a0.x); fma2(macc1[1], x10, a0.y);
            fma2(macc1[2], x10, a1.x); fma2(macc1[3], x10, a1.y);
            fma2(macc1[4], x10, a2.x); fma2(macc1[5], x10, a2.y);
            fma2(macc1[6], x10, a3.x); fma2(macc1[7], x10, a3.y);
            ulonglong2 c0v = wb[0], c1v = wb[1], c2v = wb[2], c3v = wb[3];
            fma2(macc0[0], x01, c0v.x); fma2(macc0[1], x01, c0v.y);
            fma2(macc0[2], x01, c1v.x); fma2(macc0[3], x01, c1v.y);
            fma2(macc0[4], x01, c2v.x); fma2(macc0[5], x01, c2v.y);
            fma2(macc0[6], x01, c3v.x); fma2(macc0[7], x01, c3v.y);
            fma2(macc1[0], x11, c0v.x); fma2(macc1[1], x11, c0v.y);
            fma2(macc1[2], x11, c1v.x); fma2(macc1[3], x11, c1v.y);
            fma2(macc1[4], x11, c2v.x); fma2(macc1[5], x11, c2v.y);
            fma2(macc1[6], x11, c3v.x); fma2(macc1[7], x11, c3v.y);
        }
        __syncthreads();
    }

    #pragma unroll
    for (int mp = 0; mp < 8; mp++) {
        add2(macc0[mp], __shfl_xor_sync(0xffffffffu, macc0[mp], 1));
        add2(macc0[mp], __shfl_xor_sync(0xffffffffu, macc0[mp], 2));
        add2(macc0[mp], __shfl_xor_sync(0xffffffffu, macc0[mp], 4));
        add2(macc1[mp], __shfl_xor_sync(0xffffffffu, macc1[mp], 1));
        add2(macc1[mp], __shfl_xor_sync(0xffffffffu, macc1[mp], 2));
        add2(macc1[mp], __shfl_xor_sync(0xffffffffu, macc1[mp], 4));
    }
    if (cg == 0) {
        #pragma unroll
        for (int mp = 0; mp < 8; mp++) {
            float2 v0 = unpack2(macc0[mp]);
            float2 v1 = unpack2(macc1[mp]);
            float bb0 = be2[2*mp], bb1 = be2[2*mp+1];
            Ms[e0*MD + 2*mp]     = silu(v0.x + bb0);
            Ms[e0*MD + 2*mp + 1] = silu(v0.y + bb1);
            Ms[e1*MD + 2*mp]     = silu(v1.x + bb0);
            Ms[e1*MD + 2*mp + 1] = silu(v1.y + bb1);
        }
    }
    __syncthreads();
    if (tid < GN*MD) {
        int gg = tid >> 4, m = tid & 15;
        float s = 0.f;
        #pragma unroll
        for (int k2 = 0; k2 < KNB; k2++) s += Ms[(gg*KNB + k2)*MD + m];
        g_mi[(size_t)(base_gn + gg)*MD + m] = s;
    }
}

// ---------------- kernel 3b: R = m_i @ Wn1[142:158]  ------------------------
__global__ void __launch_bounds__(288)
rgemm_kernel(const float* __restrict__ Wn1) {
    __shared__ u64 mi_u[RNODES][8];
    int tid = threadIdx.x;
    size_t gn0 = (size_t)blockIdx.x * RNODES;
    for (int v = tid; v < RNODES*8; v += 288) {
        int nd = v >> 3, mp = v & 7;
        float2 m2 = *(const float2*)(g_mi + (gn0 + nd) * MD + mp * 2);
        mi_u[nd][mp] = pack2(m2.x, m2.y);
    }
    __syncthreads();
    if (tid >= 284) return;
    int c = tid;
    u64 w[8];
    #pragma unroll
    for (int m = 0; m < 8; m++) {
        float w0 = Wn1[(size_t)(DD + 2*m)     * 284 + c];
        float w1 = Wn1[(size_t)(DD + 2*m + 1) * 284 + c];
        w[m] = pack2(w0, w1);
    }
    for (int nd = 0; nd < RNODES; nd++) {
        u64 acc = 0ull;
        #pragma unroll
        for (int m = 0; m < 8; m++) fma2(acc, mi_u[nd][m], w[m]);
        float2 v = unpack2(acc);
        g_R[(gn0 + nd) * QS + c] = v.x + v.y;
    }
}

// ---------------- kernel 4: LN stats + elementwise h + partial sums ----------
__global__ void __launch_bounds__(256)
node_kernel(const float* __restrict__ feats) {
    __shared__ float f_s [8 * 144];
    __shared__ float h_s [8 * 288];
    __shared__ float inv_s[8], bt_s[8];
    int tid = threadIdx.x;
    int base_gn = blockIdx.x * 8;
    int w = tid >> 5, lane = tid & 31;

    {
        int gn = base_gn + w;
        const float* fp = feats + (size_t)gn * DD;
        float s = 0.f, ss = 0.f;
        float vals[5];
        #pragma unroll
        for (int u = 0; u < 5; u++) {
            int c = lane + u * 32;
            float v = (c < DD) ? fp[c] : 0.f;
            vals[u] = v; s += v; ss += v * v;
        }
        #pragma unroll
        for (int o = 16; o; o >>= 1) {
            s  += __shfl_xor_sync(0xffffffffu, s,  o);
            ss += __shfl_xor_sync(0xffffffffu, ss, o);
        }
        float mu  = s * (1.f / DD);
        float var = ss * (1.f / DD) - mu * mu;
        float inv = rsqrtf(var + 1e-5f);
        if (lane == 0) { inv_s[w] = inv; bt_s[w] = inv * mu; }
        #pragma unroll
        for (int u = 0; u < 5; u++) {
            int c = lane + u * 32;
            if (c < DD) f_s[w * 144 + c] = vals[u];
        }
    }
    __syncthreads();

    for (int o = tid; o < 8 * 284; o += 256) {
        int g = o / 284;
        int c = o - g * 284;
        size_t gn = base_gn + g;
        float q = g_Q[gn * QS + c];
        float r = g_R[gn * QS + c];
        float val = inv_s[g] * q - bt_s[g] * g_SWs[c] + g_bW[c] + r;
        h_s[g * 288 + c] = silu(val);
    }
    __syncthreads();

    for (int c = tid; c < 284; c += 256) {
        float s = 0.f;
        #pragma unroll
        for (int gg = 0; gg < 8; gg++) s += h_s[gg * 288 + c];
        g_hpart[(size_t)blockIdx.x * 284 + c] = s;
    }
    for (int c = tid; c < DD; c += 256) {
        float s = 0.f;
        #pragma unroll
        for (int gg = 0; gg < 8; gg++) s += f_s[gg * 144 + c];
        g_fpart[(size_t)blockIdx.x * DD + c] = s;
    }
}

// ---------------- kernel 5: pool + folded stage-2 + head ---------------------
__global__ void __launch_bounds__(256)
head_kernel(const float* __restrict__ Wn2, const float* __restrict__ bn2,
            const float* __restrict__ Wout, const float* __restrict__ bout,
            float* __restrict__ out) {
    __shared__ float H[284];
    __shared__ float F[DD];
    __shared__ float red[256];
    int b = blockIdx.x, tid = threadIdx.x;
    const int bpb = NN / 8;

    for (int c = tid; c < 284; c += 256) {
        float s = 0.f;
        const float* pp = g_hpart + ((size_t)b * bpb) * 284 + c;
        for (int blk = 0; blk < bpb; blk++) s += pp[(size_t)blk * 284];
        H[c] = s;
    }
    for (int c = tid; c < DD; c += 256) {
        float s = 0.f;
        const float* pp = g_fpart + ((size_t)b * bpb) * DD + c;
        for (int blk = 0; blk < bpb; blk++) s += pp[(size_t)blk * DD];
        F[c] = s;
    }
    __syncthreads();

    float acc = 0.f;
    for (int c = tid; c < 284; c += 256) {
        const float* wr = Wn2 + (size_t)c * DD;
        float w2o = 0.f;
        for (int d = 0; d < DD; d++) w2o += wr[d] * Wout[d];
        acc += H[c] * w2o;
    }
    for (int d = tid; d < DD; d += 256)
        acc += (F[d] + (float)NN * bn2[d]) * Wout[d];
    red[tid] = acc;
    __syncthreads();
    for (int s2 = 128; s2 > 0; s2 >>= 1) {
        if (tid < s2) red[tid] += red[tid + s2];
        __syncthreads();
    }
    if (tid == 0) out[b] = red[0] * (1.f / (float)NN) + bout[0];
}

// ---------------- launch ----------------------------------------------------
extern "C" void kernel_launch(void* const* d_in, const int* in_sizes, int n_in,
                              void* d_out, int out_size) {
    const float* feats = (const float*)d_in[0];
    const float* coors = (const float*)d_in[1];
    const float* We1  = (const float*)d_in[3];
    const float* be1  = (const float*)d_in[4];
    const float* We2  = (const float*)d_in[5];
    const float* be2  = (const float*)d_in[6];
    const float* lng  = (const float*)d_in[11];
    const float* lnb  = (const float*)d_in[12];
    const float* Wn1  = (const float*)d_in[13];
    const float* bn1  = (const float*)d_in[14];
    const float* Wn2  = (const float*)d_in[15];
    const float* bn2  = (const float*)d_in[16];
    const float* Wout = (const float*)d_in[17];
    const float* bout = (const float*)d_in[18];
    float* out = (float*)d_out;

    knn_kernel<<<(BB * NN) / 2, 256>>>(coors);
    lnfold_kernel<<<3, 96>>>(Wn1, bn1, lng, lnb);
    padw_kernel<<<(21*CPAD + CPAD*MD + 255) / 256, 256>>>(We1, We2);
    dim3 pg(25, 256);
    prep_kernel<<<pg, 256>>>(feats, We1, be1, Wn1, lng);
    edge_kernel<<<(BB * NN) / GN, ETH>>>(be2);
    rgemm_kernel<<<(BB * NN) / RNODES, 288>>>(Wn1);
    node_kernel<<<(BB * NN) / 8, 256>>>(feats);
    head_kernel<<<BB, 256>>>(Wn2, bn2, Wout, bout, out);
}

// round 17
// speedup vs baseline: 1.0486x; 1.0016x over previous
#include <cuda_runtime.h>
#include <math.h>

#define BB   16
#define NN   2048
#define DD   142
#define KNB  10
#define MD   16
#define EH   610
#define CPAD 640
#define QS   320
#define GN   8
#define RR   (GN*KNB)     // 80
#define ETH  320
#define RNODES 64
#define WDQ8  172
#define WE2Q8 132
#define DFS  25

typedef unsigned long long u64;

__device__ int   g_idx [BB*NN*KNB];
__device__ float g_dist[BB*NN*KNB];
__device__ float g_mi  [BB*NN*MD];
__device__ float g_hpart[(BB*NN/8)*284];
__device__ float g_fpart[(BB*NN/8)*DD];
__device__ float g_base[(size_t)BB*NN*CPAD];
__device__ float g_P   [(size_t)BB*NN*CPAD];
__device__ float g_Q   [(size_t)BB*NN*QS];
__device__ float g_R   [(size_t)BB*NN*QS];
__device__ float g_SWs [284];
__device__ float g_bW  [284];
__device__ float g_wd_pad [21*CPAD];
__device__ float g_we2_pad[CPAD*MD];

__device__ __forceinline__ float silu(float x) {
    return __fdividef(x, 1.f + __expf(-x));
}

__device__ __forceinline__ u64 pack2(float x, float y) {
    u64 r;
    asm("mov.b64 %0, {%1, %2};" : "=l"(r) : "f"(x), "f"(y));
    return r;
}
__device__ __forceinline__ void fma2(u64 &d, u64 a, u64 b) {
    asm("fma.rn.f32x2 %0, %1, %2, %0;" : "+l"(d) : "l"(a), "l"(b));
}
__device__ __forceinline__ void add2(u64 &d, u64 a) {
    asm("add.rn.f32x2 %0, %0, %1;" : "+l"(d) : "l"(a));
}
__device__ __forceinline__ float2 unpack2(u64 v) {
    float2 r;
    asm("mov.b64 {%0, %1}, %2;" : "=f"(r.x), "=f"(r.y) : "l"(v));
    return r;
}

// ---------------- kernel 1: KNN — 2 nodes per block --------------------------
__global__ void __launch_bounds__(256) knn_kernel(const float* __restrict__ coors) {
    __shared__ float sc[NN*3];
    __shared__ float swv[8];
    __shared__ int   swi[8];
    __shared__ int   s_win[2];
    int bi0 = blockIdx.x * 2;
    int b   = bi0 >> 11;
    int i0  = bi0 & (NN - 1);
    int tid = threadIdx.x, lane = tid & 31, warp = tid >> 5;
    int h   = tid >> 7;
    int lt  = tid & 127;
    const float* cb = coors + (size_t)b * NN * 3;
    for (int idx = tid; idx < NN*3; idx += 256) sc[idx] = cb[idx];
    __syncthreads();
    int i = i0 + h;
    float cx = sc[i*3+0], cy = sc[i*3+1], cz = sc[i*3+2];
    float vals[16];
    #pragma unroll
    for (int u = 0; u < 16; u++) {
        int j = u * 128 + lt;
        float dx = cx - sc[j*3+0];
        float dy = cy - sc[j*3+1];
        float dz = cz - sc[j*3+2];
        vals[u] = dx*dx + dy*dy + dz*dz;
    }
    float lmv = vals[0]; int lmu = 0;
    #pragma unroll
    for (int u = 1; u < 16; u++)
        if (vals[u] < lmv) { lmv = vals[u]; lmu = u; }

    for (int t = 0; t < KNB; t++) {
        float bv = lmv; int bj = lmu * 128 + lt;
        #pragma unroll
        for (int off = 16; off; off >>= 1) {
            float ov = __shfl_down_sync(0xffffffffu, bv, off);
            int   oj = __shfl_down_sync(0xffffffffu, bj, off);
            if (ov < bv || (ov == bv && oj < bj)) { bv = ov; bj = oj; }
        }
        if (lane == 0) { swv[warp] = bv; swi[warp] = bj; }
        __syncthreads();
        if (lt == 0) {
            int w0 = h * 4;
            float fv = swv[w0]; int fj = swi[w0];
            #pragma unroll
            for (int w = 1; w < 4; w++) {
                float ov = swv[w0 + w]; int oj = swi[w0 + w];
                if (ov < fv || (ov == fv && oj < fj)) { fv = ov; fj = oj; }
            }
            g_idx [(bi0 + h)*KNB + t] = fj;
            g_dist[(bi0 + h)*KNB + t] = fv;
            s_win[h] = fj;
        }
        __syncthreads();
        int wj = s_win[h];
        if ((wj & 127) == lt) {
            vals[wj >> 7] = INFINITY;
            lmv = vals[0]; lmu = 0;
            #pragma unroll
            for (int u = 1; u < 16; u++)
                if (vals[u] < lmv) { lmv = vals[u]; lmu = u; }
        }
    }
}

// ---------------- kernel 1b: lnfold + weight padding -------------------------
__global__ void lnfold_kernel(const float* __restrict__ Wn1,
                              const float* __restrict__ bn1,
                              const float* __restrict__ lng,
                              const float* __restrict__ lnb) {
    int c = threadIdx.x + blockIdx.x * 96;
    if (c >= 284) return;
    float a1 = 0.f, a2 = 0.f;
    for (int k = 0; k < DD; k++) {
        float w = Wn1[(size_t)k * 284 + c];
        a1 += lng[k] * w;
        a2 += lnb[k] * w;
    }
    g_SWs[c] = a1;
    g_bW[c]  = a2 + bn1[c];
}

__global__ void __launch_bounds__(256)
padw_kernel(const float* __restrict__ We1, const float* __restrict__ We2) {
    int idx = blockIdx.x * 256 + threadIdx.x;
    if (idx < 21 * CPAD) {
        int t = idx / CPAD, c = idx - t * CPAD;
        g_wd_pad[idx] = (c < EH) ? We1[(size_t)(284 + t) * EH + c] : 0.f;
    } else {
        int j = idx - 21 * CPAD;
        if (j < CPAD * MD) {
            int row = j >> 4;
            g_we2_pad[j] = (row < EH) ? We2[j] : 0.f;
        }
    }
}

// ---------------- kernel 2: prep GEMM — padded As2u (conflict-free A) --------
__global__ void __launch_bounds__(256)
prep_kernel(const float* __restrict__ feats,
            const float* __restrict__ We1, const float* __restrict__ be1,
            const float* __restrict__ Wn1, const float* __restrict__ lng) {
    __shared__ __align__(16) u64 As2u[128][19];   // pad 18->19: ty-stride bank 24
    __shared__ float Bs[16][64];
    int tid = threadIdx.x;
    int tx = tid & 7, ty = tid >> 3;
    int ct = blockIdx.x;
    size_t n0 = (size_t)blockIdx.y * 128;

    const float* src; int srcStride, rowOff, colbase, maxcol, outStride;
    float* outp; bool addBias = false; bool scaleLn = false;
    if (ct < 10) {
        src = We1; srcStride = EH; rowOff = 0; colbase = ct * 64;
        maxcol = EH; outp = g_base; outStride = CPAD; addBias = true;
    } else if (ct < 20) {
        src = We1; srcStride = EH; rowOff = DD; colbase = (ct - 10) * 64;
        maxcol = EH; outp = g_P; outStride = CPAD;
    } else {
        src = Wn1; srcStride = 284; rowOff = 0; colbase = (ct - 20) * 64;
        maxcol = 284; outp = g_Q; outStride = QS; scaleLn = true;
    }

    u64 acc[4][4];
    #pragma unroll
    for (int i = 0; i < 4; i++)
        #pragma unroll
        for (int j = 0; j < 4; j++) acc[i][j] = 0ull;

    for (int k0 = 0; k0 < DD; k0 += 16) {
        #pragma unroll
        for (int p = 0; p < 4; p++) {
            int idx = tid + p * 256;
            int node = idx >> 3, kp = (idx & 7) * 2;
            int k = k0 + kp;
            float2 v = make_float2(0.f, 0.f);
            if (k < DD)
                v = *(const float2*)(feats + (n0 + node) * DD + k);
            As2u[node][kp]     = pack2(v.x, v.x);
            As2u[node][kp + 1] = pack2(v.y, v.y);
        }
        #pragma unroll
        for (int p = 0; p < 2; p++) {
            int idx = tid + p * 256;
            int kk = idx >> 5, cpos = (idx & 31) * 2;
            int k = k0 + kk;
            int cl = colbase + cpos;
            float2 v = make_float2(0.f, 0.f);
            if (k < DD) {
                if (cl + 1 < maxcol)
                    v = *(const float2*)(src + (size_t)(rowOff + k) * srcStride + cl);
                else if (cl < maxcol)
                    v.x = src[(size_t)(rowOff + k) * srcStride + cl];
                if (scaleLn) {
                    float g = lng[k];
                    v.x *= g; v.y *= g;
                }
            }
            Bs[kk][cpos] = v.x; Bs[kk][cpos+1] = v.y;
        }
        __syncthreads();
        #pragma unroll
        for (int kk = 0; kk < 16; kk++) {
            ulonglong2 w01 = *(const ulonglong2*)&Bs[kk][tx*4];
            ulonglong2 w23 = *(const ulonglong2*)&Bs[kk][32 + tx*4];
            #pragma unroll
            for (int i = 0; i < 4; i++) {
                u64 pa = As2u[ty*4 + i][kk];
                fma2(acc[i][0], pa, w01.x);
                fma2(acc[i][1], pa, w01.y);
                fma2(acc[i][2], pa, w23.x);
                fma2(acc[i][3], pa, w23.y);
            }
        }
        __syncthreads();
    }

    #pragma unroll
    for (int i = 0; i < 4; i++) {
        size_t node = n0 + ty*4 + i;
        float ov[8];
        #pragma unroll
        for (int j = 0; j < 4; j++) {
            float2 v = unpack2(acc[i][j]);
            ov[2*j] = v.x; ov[2*j+1] = v.y;
        }
        #pragma unroll
        for (int j = 0; j < 4; j++) {
            int cl = colbase + tx*4 + j;
            float val = 0.f;
            if (cl < maxcol) {
                val = ov[j];
                if (addBias) val += be1[cl];
            }
            ov[j] = val;
        }
        #pragma unroll
        for (int j = 4; j < 8; j++) {
            int cl = colbase + 32 + tx*4 + (j - 4);
            float val = 0.f;
            if (cl < maxcol) {
                val = ov[j];
                if (addBias) val += be1[cl];
            }
            ov[j] = val;
        }
        float* op = outp + node * outStride + colbase;
        *(float4*)(op + tx*4)      = make_float4(ov[0], ov[1], ov[2], ov[3]);
        *(float4*)(op + 32 + tx*4) = make_float4(ov[4], ov[5], ov[6], ov[7]);
    }
}

// ---------------- kernel 3: edge — R16 (padded-weight staging) ---------------
__global__ void __launch_bounds__(ETH, 2)
edge_kernel(const float* __restrict__ be2) {
    __shared__ int   sj [RR];
    __shared__ float sdt[RR];
    __shared__ float df_s[RR*DFS];
    __shared__ __align__(16) float wd_s[8*WDQ8];
    __shared__ __align__(16) float we2_s[8*WE2Q8];
    __shared__ __align__(16) float base_s[GN*68];
    __shared__ float Ms[RR*MD];

    int tid = threadIdx.x;
    int base_gn = blockIdx.x * GN;
    int b = base_gn >> 11;
    int cg = tid & 7;
    int pp = tid >> 3;
    int g  = pp / 5;
    int pl = pp % 5;
    int e0 = g * 10 + 2 * pl;
    int e1 = e0 + 1;

    if (tid < RR) {
        sj [tid] = g_idx [base_gn*KNB + tid];
        sdt[tid] = g_dist[base_gn*KNB + tid];
    }
    __syncthreads();

    for (int v = tid; v < RR*21; v += ETH) {
        int ee = v / 21, t = v - ee*21;
        float d = sdt[ee];
        float f;
        if (t < 10)      f = sinf(ldexpf(d, -t));
        else if (t < 20) f = cosf(ldexpf(d, -(t-10)));
        else             f = d;
        df_s[ee*DFS + t] = f;
    }

    size_t jg0 = (size_t)((b << 11) + sj[e0]);
    size_t jg1 = (size_t)((b << 11) + sj[e1]);
    u64 macc0[8] = {0,0,0,0,0,0,0,0};
    u64 macc1[8] = {0,0,0,0,0,0,0,0};

    for (int chunk = 0; chunk < 10; chunk++) {
        int c0 = chunk * 64;
        for (int v = tid; v < 21*32; v += ETH) {
            int t = v / 32, c = (v - t*32) * 2;
            float2 w = *(const float2*)(g_wd_pad + t*CPAD + c0 + c);
            int q = c >> 3, lq = c & 7;
            wd_s[q*WDQ8 + t*8 + lq]     = w.x;
            wd_s[q*WDQ8 + t*8 + lq + 1] = w.y;
        }
        for (int v = tid; v < 64*MD/4; v += ETH) {
            int off = v * 4;
            int row = off >> 4, m = off & 15;
            float4 w = *(const float4*)(g_we2_pad + (size_t)(c0 + row) * MD + m);
            int q = row >> 3, lr = row & 7;
            *(float4*)(we2_s + q*WE2Q8 + lr*16 + m) = w;
        }
        for (int v = tid; v < GN*64/4; v += ETH) {
            int off = v * 4;
            int gg = off >> 6, c = off & 63;
            *(float4*)(base_s + gg*68 + c) =
                *(const float4*)(g_base + (size_t)(base_gn + gg) * CPAD + c0 + c);
        }
        __syncthreads();

        const float4* bp4 = (const float4*)(base_s + g*68 + cg*8);
        float4 b0 = bp4[0], b1 = bp4[1];
        const float4* pr0 = (const float4*)(g_P + jg0 * CPAD + c0 + cg*8);
        const float4* pr1 = (const float4*)(g_P + jg1 * CPAD + c0 + cg*8);
        u64 h0[4], h1[4];
        {
            float4 p0 = pr0[0], p1 = pr0[1];
            h0[0] = pack2(b0.x + p0.x, b0.y + p0.y);
            h0[1] = pack2(b0.z + p0.z, b0.w + p0.w);
            h0[2] = pack2(b1.x + p1.x, b1.y + p1.y);
            h0[3] = pack2(b1.z + p1.z, b1.w + p1.w);
        }
        {
            float4 p0 = pr1[0], p1 = pr1[1];
            h1[0] = pack2(b0.x + p0.x, b0.y + p0.y);
            h1[1] = pack2(b0.z + p0.z, b0.w + p0.w);
            h1[2] = pack2(b1.x + p1.x, b1.y + p1.y);
            h1[3] = pack2(b1.z + p1.z, b1.w + p1.w);
        }

        const float* dfp0 = df_s + e0*DFS;
        const float* dfp1 = df_s + e1*DFS;
        const float* wdq = wd_s + cg*WDQ8;
        #pragma unroll
        for (int t = 0; t < 21; t++) {
            const ulonglong2* wr = (const ulonglong2*)(wdq + t*8);
            u64 d0 = pack2(dfp0[t], dfp0[t]);
            u64 d1 = pack2(dfp1[t], dfp1[t]);
            ulonglong2 wA = wr[0], wB = wr[1];
            fma2(h0[0], d0, wA.x); fma2(h0[1], d0, wA.y);
            fma2(h0[2], d0, wB.x); fma2(h0[3], d0, wB.y);
            fma2(h1[0], d1, wA.x); fma2(h1[1], d1, wA.y);
            fma2(h1[2], d1, wB.x); fma2(h1[3], d1, wB.y);
        }
        const float* weq = we2_s + cg*WE2Q8;
        #pragma unroll
        for (int cp = 0; cp < 4; cp++) {
            const ulonglong2* wa = (const ulonglong2*)(weq + 2*cp*16);
            const ulonglong2* wb = (const ulonglong2*)(weq + 2*cp*16 + 16);
            float2 v0 = unpack2(h0[cp]);
            float2 v1 = unpack2(h1[cp]);
            u64 x00 = pack2(silu(v0.x), silu(v0.x));
            u64 x01 = pack2(silu(v0.y), silu(v0.y));
            u64 x10 = pack2(silu(v1.x), silu(v1.x));
            u64 x11 = pack2(silu(v1.y), silu(v1.y));
            ulonglong2 a0 = wa[0], a1 = wa[1], a2 = wa[2], a3 = wa[3];
            fma2(macc0[0], x00, a0.x); fma2(macc0[1], x00, a0.y);
            fma2(macc0[2], x00, a1.x); fma2(macc0[3], x00, a1.y);
            fma2(macc0[4], x00, a2.x); fma2(macc0[5], x00, a2.y);
            fma2(macc0[6], x00, a3.x); fma2(macc0[7], x00, a3.y);
            fma2(macc1[0], x10, a0.x); fma2(macc1[1], x10, a0.y);
            fma2(macc1[2], x10, a1.x); fma2(macc1[3], x10, a1.y);
            fma2(macc1[4], x10, a2.x); fma2(macc1[5], x10, a2.y);
            fma2(macc1[6], x10, a3.x); fma2(macc1[7], x10, a3.y);
            ulonglong2 c0v = wb[0], c1v = wb[1], c2v = wb[2], c3v = wb[3];
            fma2(macc0[0], x01, c0v.x); fma2(macc0[1], x01, c0v.y);
            fma2(macc0[2], x01, c1v.x); fma2(macc0[3], x01, c1v.y);
            fma2(macc0[4], x01, c2v.x); fma2(macc0[5], x01, c2v.y);
            fma2(macc0[6], x01, c3v.x); fma2(macc0[7], x01, c3v.y);
            fma2(macc1[0], x11, c0v.x); fma2(macc1[1], x11, c0v.y);
            fma2(macc1[2], x11, c1v.x); fma2(macc1[3], x11, c1v.y);
            fma2(macc1[4], x11, c2v.x); fma2(macc1[5], x11, c2v.y);
            fma2(macc1[6], x11, c3v.x); fma2(macc1[7], x11, c3v.y);
        }
        __syncthreads();
    }

    #pragma unroll
    for (int mp = 0; mp < 8; mp++) {
        add2(macc0[mp], __shfl_xor_sync(0xffffffffu, macc0[mp], 1));
        add2(macc0[mp], __shfl_xor_sync(0xffffffffu, macc0[mp], 2));
        add2(macc0[mp], __shfl_xor_sync(0xffffffffu, macc0[mp], 4));
        add2(macc1[mp], __shfl_xor_sync(0xffffffffu, macc1[mp], 1));
        add2(macc1[mp], __shfl_xor_sync(0xffffffffu, macc1[mp], 2));
        add2(macc1[mp], __shfl_xor_sync(0xffffffffu, macc1[mp], 4));
    }
    if (cg == 0) {
        #pragma unroll
        for (int mp = 0; mp < 8; mp++) {
            float2 v0 = unpack2(macc0[mp]);
            float2 v1 = unpack2(macc1[mp]);
            float bb0 = be2[2*mp], bb1 = be2[2*mp+1];
            Ms[e0*MD + 2*mp]     = silu(v0.x + bb0);
            Ms[e0*MD + 2*mp + 1] = silu(v0.y + bb1);
            Ms[e1*MD + 2*mp]     = silu(v1.x + bb0);
            Ms[e1*MD + 2*mp + 1] = silu(v1.y + bb1);
        }
    }
    __syncthreads();
    if (tid < GN*MD) {
        int gg = tid >> 4, m = tid & 15;
        float s = 0.f;
        #pragma unroll
        for (int k2 = 0; k2 < KNB; k2++) s += Ms[(gg*KNB + k2)*MD + m];
        g_mi[(size_t)(base_gn + gg)*MD + m] = s;
    }
}

// ---------------- kernel 3b: R = m_i @ Wn1[142:158]  ------------------------
__global__ void __launch_bounds__(288)
rgemm_kernel(const float* __restrict__ Wn1) {
    __shared__ u64 mi_u[RNODES][8];
    int tid = threadIdx.x;
    size_t gn0 = (size_t)blockIdx.x * RNODES;
    for (int v = tid; v < RNODES*8; v += 288) {
        int nd = v >> 3, mp = v & 7;
        float2 m2 = *(const float2*)(g_mi + (gn0 + nd) * MD + mp * 2);
        mi_u[nd][mp] = pack2(m2.x, m2.y);
    }
    __syncthreads();
    if (tid >= 284) return;
    int c = tid;
    u64 w[8];
    #pragma unroll
    for (int m = 0; m < 8; m++) {
        float w0 = Wn1[(size_t)(DD + 2*m)     * 284 + c];
        float w1 = Wn1[(size_t)(DD + 2*m + 1) * 284 + c];
        w[m] = pack2(w0, w1);
    }
    for (int nd = 0; nd < RNODES; nd++) {
        u64 acc = 0ull;
        #pragma unroll
        for (int m = 0; m < 8; m++) fma2(acc, mi_u[nd][m], w[m]);
        float2 v = unpack2(acc);
        g_R[(gn0 + nd) * QS + c] = v.x + v.y;
    }
}

// ---------------- kernel 4: LN stats + elementwise h + partial sums ----------
__global__ void __launch_bounds__(256)
node_kernel(const float* __restrict__ feats) {
    __shared__ float f_s [8 * 144];
    __shared__ float h_s [8 * 288];
    __shared__ float inv_s[8], bt_s[8];
    int tid = threadIdx.x;
    int base_gn = blockIdx.x * 8;
    int w = tid >> 5, lane = tid & 31;

    {
        int gn = base_gn + w;
        const float* fp = feats + (size_t)gn * DD;
        float s = 0.f, ss = 0.f;
        float vals[5];
        #pragma unroll
        for (int u = 0; u < 5; u++) {
            int c = lane + u * 32;
            float v = (c < DD) ? fp[c] : 0.f;
            vals[u] = v; s += v; ss += v * v;
        }
        #pragma unroll
        for (int o = 16; o; o >>= 1) {
            s  += __shfl_xor_sync(0xffffffffu, s,  o);
            ss += __shfl_xor_sync(0xffffffffu, ss, o);
        }
        float mu  = s * (1.f / DD);
        float var = ss * (1.f / DD) - mu * mu;
        float inv = rsqrtf(var + 1e-5f);
        if (lane == 0) { inv_s[w] = inv; bt_s[w] = inv * mu; }
        #pragma unroll
        for (int u = 0; u < 5; u++) {
            int c = lane + u * 32;
            if (c < DD) f_s[w * 144 + c] = vals[u];
        }
    }
    __syncthreads();

    for (int o = tid; o < 8 * 284; o += 256) {
        int g = o / 284;
        int c = o - g * 284;
        size_t gn = base_gn + g;
        float q = g_Q[gn * QS + c];
        float r = g_R[gn * QS + c];
        float val = inv_s[g] * q - bt_s[g] * g_SWs[c] + g_bW[c] + r;
        h_s[g * 288 + c] = silu(val);
    }
    __syncthreads();

    for (int c = tid; c < 284; c += 256) {
        float s = 0.f;
        #pragma unroll
        for (int gg = 0; gg < 8; gg++) s += h_s[gg * 288 + c];
        g_hpart[(size_t)blockIdx.x * 284 + c] = s;
    }
    for (int c = tid; c < DD; c += 256) {
        float s = 0.f;
        #pragma unroll
        for (int gg = 0; gg < 8; gg++) s += f_s[gg * 144 + c];
        g_fpart[(size_t)blockIdx.x * DD + c] = s;
    }
}

// ---------------- kernel 5: pool + folded stage-2 + head ---------------------
__global__ void __launch_bounds__(256)
head_kernel(const float* __restrict__ Wn2, const float* __restrict__ bn2,
            const float* __restrict__ Wout, const float* __restrict__ bout,
            float* __restrict__ out) {
    __shared__ float H[284];
    __shared__ float F[DD];
    __shared__ float red[256];
    int b = blockIdx.x, tid = threadIdx.x;
    const int bpb = NN / 8;

    for (int c = tid; c < 284; c += 256) {
        float s = 0.f;
        const float* pp = g_hpart + ((size_t)b * bpb) * 284 + c;
        for (int blk = 0; blk < bpb; blk++) s += pp[(size_t)blk * 284];
        H[c] = s;
    }
    for (int c = tid; c < DD; c += 256) {
        float s = 0.f;
        const float* pp = g_fpart + ((size_t)b * bpb) * DD + c;
        for (int blk = 0; blk < bpb; blk++) s += pp[(size_t)blk * DD];
        F[c] = s;
    }
    __syncthreads();

    float acc = 0.f;
    for (int c = tid; c < 284; c += 256) {
        const float* wr = Wn2 + (size_t)c * DD;
        float w2o = 0.f;
        for (int d = 0; d < DD; d++) w2o += wr[d] * Wout[d];
        acc += H[c] * w2o;
    }
    for (int d = tid; d < DD; d += 256)
        acc += (F[d] + (float)NN * bn2[d]) * Wout[d];
    red[tid] = acc;
    __syncthreads();
    for (int s2 = 128; s2 > 0; s2 >>= 1) {
        if (tid < s2) red[tid] += red[tid + s2];
        __syncthreads();
    }
    if (tid == 0) out[b] = red[0] * (1.f / (float)NN) + bout[0];
}

// ---------------- launch ----------------------------------------------------
extern "C" void kernel_launch(void* const* d_in, const int* in_sizes, int n_in,
                              void* d_out, int out_size) {
    const float* feats = (const float*)d_in[0];
    const float* coors = (const float*)d_in[1];
    const float* We1  = (const float*)d_in[3];
    const float* be1  = (const float*)d_in[4];
    const float* We2  = (const float*)d_in[5];
    const float* be2  = (const float*)d_in[6];
    const float* lng  = (const float*)d_in[11];
    const float* lnb  = (const float*)d_in[12];
    const float* Wn1  = (const float*)d_in[13];
    const float* bn1  = (const float*)d_in[14];
    const float* Wn2  = (const float*)d_in[15];
    const float* bn2  = (const float*)d_in[16];
    const float* Wout = (const float*)d_in[17];
    const float* bout = (const float*)d_in[18];
    float* out = (float*)d_out;

    knn_kernel<<<(BB * NN) / 2, 256>>>(coors);
    lnfold_kernel<<<3, 96>>>(Wn1, bn1, lng, lnb);
    padw_kernel<<<(21*CPAD + CPAD*MD + 255) / 256, 256>>>(We1, We2);
    dim3 pg(25, 256);
    prep_kernel<<<pg, 256>>>(feats, We1, be1, Wn1, lng);
    edge_kernel<<<(BB * NN) / GN, ETH>>>(be2);
    rgemm_kernel<<<(BB * NN) / RNODES, 288>>>(Wn1);
    node_kernel<<<(BB * NN) / 8, 256>>>(feats);
    head_kernel<<<BB, 256>>>(Wn2, bn2, Wout, bout, out);
}